// round 7
// baseline (speedup 1.0000x reference)
#include <cuda_runtime.h>
#include <cstdint>

#define NB   4
#define IC   256
#define OC   128
#define IH   32
#define IW   88
#define NPIX (IH*IW)          // 2816
#define OW   496
#define OH   432
#define ROWS_PER_CHUNK 27
#define NCHUNK (OH / ROWS_PER_CHUNK)   // 16

// Scratch (no cudaMalloc allowed): context after GEMM. L2-resident (5.77 MB).
__device__ float g_ctx[NB*OC*NPIX];

// Packed fp32x2 helpers (base sm_100-family PTX, not 'a'-gated).
#define FFMA2(acc, a, b) \
    asm("fma.rn.f32x2 %0, %1, %2, %0;" : "+l"(acc) : "l"(a), "l"(b))
#define DUP_F32X2(out, v) \
    asm("mov.b64 %0, {%1, %1};" : "=l"(out) : "f"(v))
#define UNPACK_F32X2(lo, hi, in) \
    asm("mov.b64 {%0, %1}, %2;" : "=f"(lo), "=f"(hi) : "l"(in))

// ---------------------------------------------------------------------------
// Kernel 1: ctx = (Wc[64:192] @ feat + bc[64:192]) / 64
// (mean of softmax over 64 depth channels is exactly 1/64 -> depth branch gone)
// Tile M=128 x N=32, Kc=32 -> 352 CTAs (2+/SM for latency hiding).
// 256 threads, each 8m x 2n via 8 packed FFMA2 per k.
// ---------------------------------------------------------------------------
__global__ __launch_bounds__(256) void gemm_ctx_kernel(const float* __restrict__ feat,
                                                       const float* __restrict__ Wc,
                                                       const float* __restrict__ bc) {
    __shared__ __align__(16) float As[32][132];  // [k][m], padded
    __shared__ __align__(16) float Bs[32][36];   // [k][n], padded

    const int tid = threadIdx.x;
    const int nh  = tid & 15;          // n-pair index 0..15
    const int ty  = tid >> 4;          // m-octet index 0..15
    const int m0  = ty * 8;
    const int n0  = nh * 2;
    const int b   = blockIdx.y;
    const int nb  = blockIdx.x * 32;   // pixel-tile base within batch

    const float* featB = feat + (size_t)b * IC * NPIX;

    unsigned long long acc[4][2];      // [m-pair][n], each = (f32 m-even, m-odd)
#pragma unroll
    for (int p = 0; p < 4; p++) { acc[p][0] = 0ULL; acc[p][1] = 0ULL; }

    for (int kt = 0; kt < IC; kt += 32) {
        // A tile: Wc rows 64..191, cols kt..kt+31, transposed into As[k][m]
#pragma unroll
        for (int l = 0; l < 4; l++) {
            int idx = l * 256 + tid;
            int m   = idx >> 3;
            int k4  = idx & 7;
            float4 v = *(const float4*)(Wc + (size_t)(64 + m) * IC + kt + k4 * 4);
            As[k4 * 4 + 0][m] = v.x;
            As[k4 * 4 + 1][m] = v.y;
            As[k4 * 4 + 2][m] = v.z;
            As[k4 * 4 + 3][m] = v.w;
        }
        // B tile: feat[b, kt..kt+31, nb..nb+31] (256 float4 by 256 threads)
        {
            int kk = tid >> 3;
            int c4 = tid & 7;
            float4 v = *(const float4*)(featB + (size_t)(kt + kk) * NPIX + nb + c4 * 4);
            *(float4*)&Bs[kk][c4 * 4] = v;
        }
        __syncthreads();

#pragma unroll
        for (int k = 0; k < 32; k++) {
            ulonglong2 a01 = *(const ulonglong2*)&As[k][m0];
            ulonglong2 a23 = *(const ulonglong2*)&As[k][m0 + 4];
            float2 bv = *(const float2*)&Bs[k][n0];
            unsigned long long bd0, bd1;
            DUP_F32X2(bd0, bv.x);
            DUP_F32X2(bd1, bv.y);
            FFMA2(acc[0][0], a01.x, bd0); FFMA2(acc[0][1], a01.x, bd1);
            FFMA2(acc[1][0], a01.y, bd0); FFMA2(acc[1][1], a01.y, bd1);
            FFMA2(acc[2][0], a23.x, bd0); FFMA2(acc[2][1], a23.x, bd1);
            FFMA2(acc[3][0], a23.y, bd0); FFMA2(acc[3][1], a23.y, bd1);
        }
        __syncthreads();
    }

    const float s = 1.0f / 64.0f;
#pragma unroll
    for (int p = 0; p < 4; p++) {
        float lo0, hi0, lo1, hi1;
        UNPACK_F32X2(lo0, hi0, acc[p][0]);
        UNPACK_F32X2(lo1, hi1, acc[p][1]);
        int mlo = m0 + 2 * p;
        float blo = __ldg(bc + 64 + mlo);
        float bhi = __ldg(bc + 64 + mlo + 1);
        float2 olo = make_float2((lo0 + blo) * s, (lo1 + blo) * s);
        float2 ohi = make_float2((hi0 + bhi) * s, (hi1 + bhi) * s);
        *(float2*)&g_ctx[((size_t)(b * OC + mlo)) * NPIX + nb + n0]     = olo;
        *(float2*)&g_ctx[((size_t)(b * OC + mlo + 1)) * NPIX + nb + n0] = ohi;
    }
}

// ---------------------------------------------------------------------------
// Kernel 2: fused separable bilinear (32,88) -> (432,496), half-pixel + clamp.
// Exact integer segmentation: y_i = (4i-25)/54 exactly, so rows sharing the
// same source-row pair form <=3 contiguous segments per 27-row chunk. Each
// segment uses STATIC register pairs (no dynamic r[sidx] -> no SEL storm).
// Body per row: 4 FFMA + 1 STG.128 + wy FMA.
// ---------------------------------------------------------------------------
__device__ __forceinline__ void emit_rows(float4*& outp, int i, int iend,
                                          float4 a, float4 d, int t) {
    // wy = (4i-25)/54 - t
    float wy  = fmaf((float)i, 4.0f / 54.0f, -25.0f / 54.0f - (float)t);
    const float dwy = 4.0f / 54.0f;
    for (; i < iend; i++) {
        float4 o;
        o.x = fmaf(wy, d.x, a.x);
        o.y = fmaf(wy, d.y, a.y);
        o.z = fmaf(wy, d.z, a.z);
        o.w = fmaf(wy, d.w, a.w);
        __stcs(outp, o);
        outp += OW / 4;
        wy += dwy;
    }
}

__global__ __launch_bounds__(128) void resize_fused_kernel(float* __restrict__ out) {
    const int p  = blockIdx.x;             // 0..511 (b*128 + c)
    const int i0 = blockIdx.y * ROWS_PER_CHUNK;
    const int tx = threadIdx.x;

    __shared__ float raw[4][IW];

    // k0 = floor((4*i0-25)/54); numerator can be negative only for i0=0.
    int num = 4 * i0 - 25;
    int k0  = (num >= 0) ? (num / 54) : -((-num + 53) / 54);

    const float* base = g_ctx + (size_t)p * NPIX;
    for (int idx = tx; idx < 4 * IW; idx += 128) {
        int t = idx / IW;
        int j = idx - t * IW;
        int row = min(IH - 1, max(0, k0 + t));
        raw[t][j] = base[row * IW + j];
    }
    __syncthreads();

    if (tx >= OW / 4) return;

    // W-interpolation into registers (exact: x_j = (22j-51)/124).
    const int j0 = tx * 4;
    float4 r[4];
#pragma unroll
    for (int t = 0; t < 4; t++) {
        float v[4];
#pragma unroll
        for (int q = 0; q < 4; q++) {
            int xn  = 22 * (j0 + q) - 51;                    // 124*x
            int x0i = (xn >= 0) ? (xn / 124) : -((-xn + 123) / 124);
            float wx = (float)(xn - 124 * x0i) * (1.0f / 124.0f);
            int ia = min(IW - 1, max(0, x0i));
            int ib = min(IW - 1, max(0, x0i + 1));
            float a = raw[t][ia];
            float bq = raw[t][ib];
            v[q] = fmaf(wx, bq - a, a);
        }
        r[t] = make_float4(v[0], v[1], v[2], v[3]);
    }

    float4 d0 = make_float4(r[1].x - r[0].x, r[1].y - r[0].y, r[1].z - r[0].z, r[1].w - r[0].w);
    float4 d1 = make_float4(r[2].x - r[1].x, r[2].y - r[1].y, r[2].z - r[1].z, r[2].w - r[1].w);
    float4 d2 = make_float4(r[3].x - r[2].x, r[3].y - r[2].y, r[3].z - r[2].z, r[3].w - r[2].w);

    // Segment boundaries: first i with floor((4i-25)/54) >= t is ceil((54t+25)/4).
    const int iend = i0 + ROWS_PER_CHUNK;
    int i1 = (54 * (k0 + 1) + 25 + 3) >> 2;       // k0+1 >= 0 so numerator > 0
    int i2 = (54 * (k0 + 2) + 25 + 3) >> 2;
    i1 = min(max(i1, i0), iend);
    i2 = min(max(i2, i1), iend);

    float4* outp = (float4*)(out + (size_t)p * OH * OW) + (size_t)i0 * (OW / 4) + tx;
    emit_rows(outp, i0, i1, r[0], d0, k0);
    emit_rows(outp, i1, i2, r[1], d1, k0 + 1);
    emit_rows(outp, i2, iend, r[2], d2, k0 + 2);
}

// ---------------------------------------------------------------------------
extern "C" void kernel_launch(void* const* d_in, const int* in_sizes, int n_in,
                              void* d_out, int out_size) {
    const float* feat = (const float*)d_in[0];   // [4,256,32,88]
    const float* Wc   = (const float*)d_in[1];   // [192,256]
    const float* bc   = (const float*)d_in[2];   // [192]
    float* out        = (float*)d_out;           // [4,128,432,496]

    gemm_ctx_kernel<<<dim3(NPIX / 32, NB), 256>>>(feat, Wc, bc);
    resize_fused_kernel<<<dim3(NB * OC, NCHUNK), 128>>>(out);
}